// round 15
// baseline (speedup 1.0000x reference)
#include <cuda_runtime.h>
#include <cstdint>
#include <cstddef>

typedef unsigned long long ull;

#define DEV_INLINE __device__ __forceinline__

DEV_INLINE ull pack2u(unsigned lo, unsigned hi) {
    ull r; asm("mov.b64 %0, {%1, %2};" : "=l"(r) : "r"(lo), "r"(hi)); return r;
}
DEV_INLINE unsigned tf32_(float x) {
    unsigned r; asm("cvt.rna.tf32.f32 %0, %1;" : "=r"(r) : "f"(x)); return r;
}
DEV_INLINE void split_(float v, unsigned& hi, unsigned& lo) {
    hi = tf32_(v);
    lo = tf32_(v - __uint_as_float(hi));
}
DEV_INLINE void mma_tf32(float* c, const unsigned* a, unsigned b0, unsigned b1) {
    asm("mma.sync.aligned.m16n8k8.row.col.f32.tf32.tf32.f32 "
        "{%0,%1,%2,%3}, {%4,%5,%6,%7}, {%8,%9}, {%0,%1,%2,%3};"
        : "+f"(c[0]), "+f"(c[1]), "+f"(c[2]), "+f"(c[3])
        : "r"(a[0]), "r"(a[1]), "r"(a[2]), "r"(a[3]), "r"(b0), "r"(b1));
}
DEV_INLINE float sigm_(float x) { float e = __expf(-x); return __fdividef(1.f, 1.f + e); }
DEV_INLINE float tanh_(float a) { float t = __expf(-2.f * a); return __fdividef(1.f - t, 1.f + t); }

#define BB 256
#define TT 512
#define HH 256
#define G3 768

__device__ float g_xg[(size_t)BB * TT * G3];
__device__ float g_out0[(size_t)BB * TT * HH];
__device__ float g_hT[BB * HH];

// ---------------------------------------------------------------------------
// tf32 tensor-core GEMM, register-prefetch pipeline + fused K-padding (R14).
// ---------------------------------------------------------------------------
#define TSTR 136

__global__ __launch_bounds__(256, 2) void gemm_tf32(
    const float* __restrict__ A, const float* __restrict__ W,
    const float* __restrict__ bias, float* __restrict__ C,
    int M, int N, int Kiter, int Ksrc)
{
    __shared__ unsigned As[16][TSTR];
    __shared__ unsigned Bs[16][TSTR];

    const int tid = threadIdx.x;
    const int lane = tid & 31;
    const int wid = tid >> 5;
    const int wm = wid & 1;
    const int wn = wid >> 1;
    const int g  = lane >> 2;
    const int tg = lane & 3;
    const int mb = blockIdx.x * 128;
    const int nb = blockIdx.y * 128;

    const int fr = tid >> 1;
    const int fk = (tid & 1) * 8;

    const bool kvec = ((Ksrc & 3) == 0);

    const float* apb = A + (size_t)(mb + fr) * Ksrc + fk;
    const float* wpb = W + (size_t)(nb + fr) * Ksrc + fk;

    float c[4][4][4];
#pragma unroll
    for (int i = 0; i < 4; ++i)
#pragma unroll
        for (int j = 0; j < 4; ++j)
#pragma unroll
            for (int q = 0; q < 4; ++q) c[i][j][q] = 0.f;

    float av[8], wv[8];
    if (kvec) {
        float4 a0 = *(const float4*)(apb);
        float4 a1 = *(const float4*)(apb + 4);
        float4 w0 = *(const float4*)(wpb);
        float4 w1 = *(const float4*)(wpb + 4);
        av[0]=a0.x; av[1]=a0.y; av[2]=a0.z; av[3]=a0.w;
        av[4]=a1.x; av[5]=a1.y; av[6]=a1.z; av[7]=a1.w;
        wv[0]=w0.x; wv[1]=w0.y; wv[2]=w0.z; wv[3]=w0.w;
        wv[4]=w1.x; wv[5]=w1.y; wv[6]=w1.z; wv[7]=w1.w;
    } else {
#pragma unroll
        for (int j = 0; j < 8; ++j) {
            bool ok = (fk + j) < Ksrc;
            av[j] = ok ? apb[j] : 0.f;
            wv[j] = ok ? wpb[j] : 0.f;
        }
    }

    for (int k0 = 0; k0 < Kiter; k0 += 16) {
#pragma unroll
        for (int j = 0; j < 8; ++j) {
            As[fk + j][fr] = tf32_(av[j]);
            Bs[fk + j][fr] = tf32_(wv[j]);
        }
        __syncthreads();

        if (k0 + 16 < Kiter) {
            if (kvec) {
                float4 a0 = *(const float4*)(apb + k0 + 16);
                float4 a1 = *(const float4*)(apb + k0 + 20);
                float4 w0 = *(const float4*)(wpb + k0 + 16);
                float4 w1 = *(const float4*)(wpb + k0 + 20);
                av[0]=a0.x; av[1]=a0.y; av[2]=a0.z; av[3]=a0.w;
                av[4]=a1.x; av[5]=a1.y; av[6]=a1.z; av[7]=a1.w;
                wv[0]=w0.x; wv[1]=w0.y; wv[2]=w0.z; wv[3]=w0.w;
                wv[4]=w1.x; wv[5]=w1.y; wv[6]=w1.z; wv[7]=w1.w;
            } else {
#pragma unroll
                for (int j = 0; j < 8; ++j) {
                    bool ok = (k0 + 16 + fk + j) < Ksrc;
                    av[j] = ok ? apb[k0 + 16 + j] : 0.f;
                    wv[j] = ok ? wpb[k0 + 16 + j] : 0.f;
                }
            }
        }

#pragma unroll
        for (int ks = 0; ks < 2; ++ks) {
            const int kk = ks * 8;
            unsigned bf[4][2];
#pragma unroll
            for (int j = 0; j < 4; ++j) {
                int cb = wn * 32 + j * 8 + g;
                bf[j][0] = Bs[kk + tg][cb];
                bf[j][1] = Bs[kk + tg + 4][cb];
            }
#pragma unroll
            for (int i = 0; i < 4; ++i) {
                int rb = wm * 64 + i * 16;
                unsigned af[4];
                af[0] = As[kk + tg][rb + g];
                af[1] = As[kk + tg][rb + g + 8];
                af[2] = As[kk + tg + 4][rb + g];
                af[3] = As[kk + tg + 4][rb + g + 8];
#pragma unroll
                for (int j = 0; j < 4; ++j)
                    mma_tf32(c[i][j], af, bf[j][0], bf[j][1]);
            }
        }
        __syncthreads();
    }

#pragma unroll
    for (int j = 0; j < 4; ++j) {
        int col = nb + wn * 32 + j * 8 + 2 * tg;
        float2 bb = *(const float2*)(bias + col);
#pragma unroll
        for (int i = 0; i < 4; ++i) {
            int row = mb + wm * 64 + i * 16 + g;
            float2 v0; v0.x = c[i][j][0] + bb.x; v0.y = c[i][j][1] + bb.y;
            float2 v1; v1.x = c[i][j][2] + bb.x; v1.y = c[i][j][3] + bb.y;
            *(float2*)(C + (size_t)row * N + col)       = v0;
            *(float2*)(C + (size_t)(row + 8) * N + col) = v1;
        }
    }
}

// ---------------------------------------------------------------------------
// Tensor-core GRU recurrence v4: two-group pipeline, HW cluster barriers.
// 16 clusters x 8 CTAs; CTA owns 32 h (96 gate rows), K=256; batches split
// A(8)/B(8), each double-buffered.  W_hh hi/lo tf32 in registers.  h rounded
// to tf32 once at broadcast; identity path fp32 in gate-thread registers.
// Sync per step: [wait][arrive] A-section [wait][arrive] B-section — each
// wait has a full group-section between its arrive and itself (fast-path),
// and each group's DSMEM drain overlaps the other group's compute.
// ---------------------------------------------------------------------------
#define CL 8
#define HB_A 0
#define HB_B 4096
#define DSM_OFF 8192
#define DH 768
#define REC_SMEM 38912

DEV_INLINE unsigned ctarank() { unsigned r; asm("mov.u32 %0, %%cluster_ctarank;" : "=r"(r)); return r; }
DEV_INLINE unsigned s2u(const void* p) {
    unsigned a;
    asm("{ .reg .u64 t; cvta.to.shared.u64 t, %1; cvt.u32.u64 %0, t; }" : "=r"(a) : "l"(p));
    return a;
}
DEV_INLINE unsigned mapa_(unsigned a, unsigned r) {
    unsigned o; asm("mapa.shared::cluster.u32 %0, %1, %2;" : "=r"(o) : "r"(a), "r"(r)); return o;
}
DEV_INLINE void st_cluster_u64(unsigned addr, ull v) {
    asm volatile("st.shared::cluster.u64 [%0], %1;" :: "r"(addr), "l"(v) : "memory");
}
DEV_INLINE void cl_arrive() { asm volatile("barrier.cluster.arrive.aligned;" ::: "memory"); }
DEV_INLINE void cl_wait()   { asm volatile("barrier.cluster.wait.aligned;"   ::: "memory"); }

__global__ __launch_bounds__(384, 1) void gru_rec_tc(
    const float* __restrict__ xg, const float* __restrict__ W_hh,
    const float* __restrict__ b_hh, float* __restrict__ out_seq,
    float* __restrict__ hT, int layer0)
{
    extern __shared__ float smem[];

    const int tid  = threadIdx.x;
    const int lane = tid & 31;
    const int wid  = tid >> 5;
    const int g    = lane >> 2;
    const int tg   = lane & 3;
    const int mg   = wid >> 1;          // m16 group 0..5
    const int kh   = wid & 1;           // K-half
    const unsigned rank = ctarank();
    const int cid  = blockIdx.x >> 3;

    // ---- W_hh fragments (hi/lo tf32) into registers ----
    unsigned whi[16][4], wlo[16][4];
    {
        int lr0 = mg * 16 + g;
        int lr1 = lr0 + 8;
        int r0 = (lr0 >> 5) * 256 + (int)rank * 32 + (lr0 & 31);
        int r1 = (lr1 >> 5) * 256 + (int)rank * 32 + (lr1 & 31);
        const float* w0 = W_hh + (size_t)r0 * 256 + kh * 128 + tg;
        const float* w1 = W_hh + (size_t)r1 * 256 + kh * 128 + tg;
#pragma unroll
        for (int i = 0; i < 16; ++i) {
            split_(w0[i * 8],     whi[i][0], wlo[i][0]);
            split_(w1[i * 8],     whi[i][1], wlo[i][1]);
            split_(w0[i * 8 + 4], whi[i][2], wlo[i][2]);
            split_(w1[i * 8 + 4], whi[i][3], wlo[i][3]);
        }
    }

    // zero buffer 0 of both groups
    for (int i = tid; i < 2048; i += 384) { smem[HB_A + i] = 0.f; smem[HB_B + i] = 0.f; }

    const unsigned smem_u = s2u(smem);

    // gate-thread state: tid<128 -> group A, 128..255 -> group B
    const int gt   = (tid < 256);
    const int grp  = tid >> 7;            // 0 or 1 (for tid<256)
    const int gtid = tid & 127;
    const int gh   = gtid >> 2;           // 0..31
    const int bp2  = gtid & 3;            // 0..3
    const int co   = 2 * bp2;
    const int hglob = (int)rank * 32 + gh;
    float bhr = 0.f, bhz = 0.f, bhn = 0.f;
    if (gt) {
        bhr = b_hh[hglob];
        bhz = b_hh[256 + hglob];
        bhn = b_hh[512 + hglob];
    }
    const int b0g = cid * 16 + grp * 8 + co;

    __syncthreads();
    cl_arrive(); cl_wait();   // gen 0: publish zeroed buffers

    const float* xrow0 = xg + (size_t)b0g * TT * G3;
    const float* xrow1 = xrow0 + (size_t)TT * G3;
    float xr0 = 0, xz0 = 0, xn0 = 0, xr1 = 0, xz1 = 0, xn1 = 0;
    float hp0 = 0.f, hp1 = 0.f;
    if (gt) {
        xr0 = xrow0[hglob]; xz0 = xrow0[256 + hglob]; xn0 = xrow0[512 + hglob];
        xr1 = xrow1[hglob]; xz1 = xrow1[256 + hglob]; xn1 = xrow1[512 + hglob];
    }

    float* dsm = smem + DSM_OFF;

    for (int t = 0; t < TT; ++t) {
        const int p = t & 1;

        if (t) {
            cl_wait();      // ensures bcastA(t-1) delivered (pairs arrive after A(t-1))
            cl_arrive();    // gen 2t
        }

        // ================= GROUP A: step t =================
        {
            float ah[4] = {0,0,0,0}, al[4] = {0,0,0,0};
            const unsigned* hk = (const unsigned*)smem + HB_A + p * 2048 + (kh * 128 + tg) * 8 + g;
#pragma unroll
            for (int i = 0; i < 16; ++i) {
                unsigned u0 = hk[i * 64];
                unsigned u1 = hk[i * 64 + 32];
                mma_tf32(ah, whi[i], u0, u1);
                mma_tf32(al, wlo[i], u0, u1);
            }
            __syncthreads();            // dsm free (prev B gates done reading)
            {
                float* dst = dsm + kh * DH + (mg * 16 + g) * 8;
                float2 t0; t0.x = ah[0] + al[0]; t0.y = ah[1] + al[1];
                float2 t1; t1.x = ah[2] + al[2]; t1.y = ah[3] + al[3];
                *(float2*)(dst + 2 * tg)      = t0;
                *(float2*)(dst + 64 + 2 * tg) = t1;
            }
            __syncthreads();

            if (gt && grp == 0) {
                const float* d0 = dsm + gh * 8 + co;
                const float* d1 = d0 + DH;
                float2 rA = *(const float2*)(d0);
                float2 rB = *(const float2*)(d1);
                float2 zA = *(const float2*)(d0 + 256);
                float2 zB = *(const float2*)(d1 + 256);
                float2 nA = *(const float2*)(d0 + 512);
                float2 nB = *(const float2*)(d1 + 512);
                float r0 = sigm_(xr0 + bhr + rA.x + rB.x);
                float z0 = sigm_(xz0 + bhz + zA.x + zB.x);
                float n0 = tanh_(xn0 + r0 * (nA.x + nB.x + bhn));
                float onew0 = (1.f - z0) * n0 + z0 * hp0;
                float r1 = sigm_(xr1 + bhr + rA.y + rB.y);
                float z1 = sigm_(xz1 + bhz + zA.y + zB.y);
                float n1 = tanh_(xn1 + r1 * (nA.y + nB.y + bhn));
                float onew1 = (1.f - z1) * n1 + z1 * hp1;
                hp0 = onew0; hp1 = onew1;

                ull pair = pack2u(tf32_(onew0), tf32_(onew1));
                unsigned loc = smem_u + (unsigned)(HB_A + (1 - p) * 2048 + hglob * 8 + co) * 4u;
#pragma unroll
                for (int q = 0; q < CL; ++q) st_cluster_u64(mapa_(loc, (unsigned)q), pair);

                // off-path: outputs + next-x prefetch
                if (layer0) {
                    out_seq[((size_t)b0g * TT + t) * HH + hglob]       = onew0;
                    out_seq[((size_t)(b0g + 1) * TT + t) * HH + hglob] = onew1;
                } else if (t == TT - 1) {
                    hT[b0g * HH + hglob]       = onew0;
                    hT[(b0g + 1) * HH + hglob] = onew1;
                }
                if (t + 1 < TT) {
                    const float* xp0 = xrow0 + (size_t)(t + 1) * G3;
                    const float* xp1 = xrow1 + (size_t)(t + 1) * G3;
                    xr0 = xp0[hglob]; xz0 = xp0[256 + hglob]; xn0 = xp0[512 + hglob];
                    xr1 = xp1[hglob]; xz1 = xp1[256 + hglob]; xn1 = xp1[512 + hglob];
                }
            }
        }

        cl_arrive();        // gen 2t+1 (releases bcastA(t))

        // ================= GROUP B: step t =================
        {
            float bh_[4] = {0,0,0,0}, bl_[4] = {0,0,0,0};
            const unsigned* hk = (const unsigned*)smem + HB_B + p * 2048 + (kh * 128 + tg) * 8 + g;
#pragma unroll
            for (int i = 0; i < 16; ++i) {
                unsigned u0 = hk[i * 64];
                unsigned u1 = hk[i * 64 + 32];
                mma_tf32(bh_, whi[i], u0, u1);
                mma_tf32(bl_, wlo[i], u0, u1);
            }
            __syncthreads();            // A gates done reading dsm
            {
                float* dst = dsm + kh * DH + (mg * 16 + g) * 8;
                float2 t0; t0.x = bh_[0] + bl_[0]; t0.y = bh_[1] + bl_[1];
                float2 t1; t1.x = bh_[2] + bl_[2]; t1.y = bh_[3] + bl_[3];
                *(float2*)(dst + 2 * tg)      = t0;
                *(float2*)(dst + 64 + 2 * tg) = t1;
            }
            __syncthreads();

            if (gt && grp == 1) {
                const float* d0 = dsm + gh * 8 + co;
                const float* d1 = d0 + DH;
                float2 rA = *(const float2*)(d0);
                float2 rB = *(const float2*)(d1);
                float2 zA = *(const float2*)(d0 + 256);
                float2 zB = *(const float2*)(d1 + 256);
                float2 nA = *(const float2*)(d0 + 512);
                float2 nB = *(const float2*)(d1 + 512);
                float r0 = sigm_(xr0 + bhr + rA.x + rB.x);
                float z0 = sigm_(xz0 + bhz + zA.x + zB.x);
                float n0 = tanh_(xn0 + r0 * (nA.x + nB.x + bhn));
                float onew0 = (1.f - z0) * n0 + z0 * hp0;
                float r1 = sigm_(xr1 + bhr + rA.y + rB.y);
                float z1 = sigm_(xz1 + bhz + zA.y + zB.y);
                float n1 = tanh_(xn1 + r1 * (nA.y + nB.y + bhn));
                float onew1 = (1.f - z1) * n1 + z1 * hp1;
                hp0 = onew0; hp1 = onew1;

                ull pair = pack2u(tf32_(onew0), tf32_(onew1));
                unsigned loc = smem_u + (unsigned)(HB_B + (1 - p) * 2048 + hglob * 8 + co) * 4u;
#pragma unroll
                for (int q = 0; q < CL; ++q) st_cluster_u64(mapa_(loc, (unsigned)q), pair);

                if (layer0) {
                    out_seq[((size_t)b0g * TT + t) * HH + hglob]       = onew0;
                    out_seq[((size_t)(b0g + 1) * TT + t) * HH + hglob] = onew1;
                } else if (t == TT - 1) {
                    hT[b0g * HH + hglob]       = onew0;
                    hT[(b0g + 1) * HH + hglob] = onew1;
                }
                if (t + 1 < TT) {
                    const float* xp0 = xrow0 + (size_t)(t + 1) * G3;
                    const float* xp1 = xrow1 + (size_t)(t + 1) * G3;
                    xr0 = xp0[hglob]; xz0 = xp0[256 + hglob]; xn0 = xp0[512 + hglob];
                    xr1 = xp1[hglob]; xz1 = xp1[256 + hglob]; xn1 = xp1[512 + hglob];
                }
            }
        }
        // loop bottom: next iteration's wait pairs gen 2t+1
    }

    cl_wait();                 // final gen: bcastB(TT-1) arrivals
    cl_arrive(); cl_wait();    // drain barrier — no CTA exits with stores in flight
}

// ---------------------------------------------------------------------------
// Launch helpers
// ---------------------------------------------------------------------------
static void launch_rec(const float* xg, const float* Whh, const float* bhh,
                       float* oseq, float* hT, int layer0)
{
    cudaFuncSetAttribute(gru_rec_tc, cudaFuncAttributeMaxDynamicSharedMemorySize, REC_SMEM);
    cudaLaunchConfig_t cfg = {};
    cfg.gridDim = dim3(128, 1, 1);
    cfg.blockDim = dim3(384, 1, 1);
    cfg.dynamicSmemBytes = REC_SMEM;
    cfg.stream = 0;
    cudaLaunchAttribute at[1];
    at[0].id = cudaLaunchAttributeClusterDimension;
    at[0].val.clusterDim.x = CL;
    at[0].val.clusterDim.y = 1;
    at[0].val.clusterDim.z = 1;
    cfg.attrs = at;
    cfg.numAttrs = 1;
    cudaLaunchKernelEx(&cfg, gru_rec_tc, xg, Whh, bhh, oseq, hT, layer0);
}

extern "C" void kernel_launch(void* const* d_in, const int* in_sizes, int n_in,
                              void* d_out, int out_size)
{
    const float* x     = (const float*)d_in[0];
    const float* W_ih0 = (const float*)d_in[1];
    const float* W_hh0 = (const float*)d_in[2];
    const float* b_ih0 = (const float*)d_in[3];
    const float* b_hh0 = (const float*)d_in[4];
    const float* W_ih1 = (const float*)d_in[5];
    const float* W_hh1 = (const float*)d_in[6];
    const float* b_ih1 = (const float*)d_in[7];
    const float* b_hh1 = (const float*)d_in[8];
    const float* fc_W  = (const float*)d_in[9];
    const float* fc_b  = (const float*)d_in[10];
    float* out = (float*)d_out;

    float *xg, *o0, *hT;
    cudaGetSymbolAddress((void**)&xg, g_xg);
    cudaGetSymbolAddress((void**)&o0, g_out0);
    cudaGetSymbolAddress((void**)&hT, g_hT);

    const int M = BB * TT;  // 131072

    gemm_tf32<<<dim3(M / 128, G3 / 128), 256>>>(x, W_ih0, b_ih0, xg, M, G3, 80, 75);
    launch_rec(xg, W_hh0, b_hh0, o0, nullptr, 1);
    gemm_tf32<<<dim3(M / 128, G3 / 128), 256>>>(o0, W_ih1, b_ih1, xg, M, G3, 256, 256);
    launch_rec(xg, W_hh1, b_hh1, nullptr, hT, 0);
    gemm_tf32<<<dim3(BB / 128, HH / 128), 256>>>(hT, fc_W, fc_b, out, BB, HH, HH, HH);
}

// round 16
// speedup vs baseline: 1.2275x; 1.2275x over previous
#include <cuda_runtime.h>
#include <cstdint>
#include <cstddef>

typedef unsigned long long ull;

#define DEV_INLINE __device__ __forceinline__

DEV_INLINE ull fma2(ull a, ull b, ull c) {
    ull d; asm("fma.rn.f32x2 %0, %1, %2, %3;" : "=l"(d) : "l"(a), "l"(b), "l"(c)); return d;
}
DEV_INLINE float2 unpk(ull v) {
    float2 f; asm("mov.b64 {%0, %1}, %2;" : "=f"(f.x), "=f"(f.y) : "l"(v)); return f;
}
DEV_INLINE unsigned tf32_(float x) {
    unsigned r; asm("cvt.rna.tf32.f32 %0, %1;" : "=r"(r) : "f"(x)); return r;
}
DEV_INLINE void mma_tf32(float* c, const unsigned* a, unsigned b0, unsigned b1) {
    asm("mma.sync.aligned.m16n8k8.row.col.f32.tf32.tf32.f32 "
        "{%0,%1,%2,%3}, {%4,%5,%6,%7}, {%8,%9}, {%0,%1,%2,%3};"
        : "+f"(c[0]), "+f"(c[1]), "+f"(c[2]), "+f"(c[3])
        : "r"(a[0]), "r"(a[1]), "r"(a[2]), "r"(a[3]), "r"(b0), "r"(b1));
}
DEV_INLINE float sigm_(float x) { float e = __expf(-x); return __fdividef(1.f, 1.f + e); }
DEV_INLINE float tanh_(float a) { float t = __expf(-2.f * a); return __fdividef(1.f - t, 1.f + t); }

#define BB 256
#define TT 512
#define HH 256
#define G3 768

__device__ float g_xg[(size_t)BB * TT * G3];
__device__ float g_out0[(size_t)BB * TT * HH];
__device__ float g_hT[BB * HH];

// ---------------------------------------------------------------------------
// tf32 tensor-core GEMM: register prefetch + 2-stage smem double buffer.
// C[M][N] = A[M][Ksrc] @ W[N][Ksrc]^T + bias[N]; Kiter >= Ksrc, mult of 16.
// One __syncthreads per k-tile; STS(next) overlaps MMA(cur).
// Dynamic smem: 2 * 2 * 16 * TSTR * 4 = 69632 B (2 CTAs/SM fit in 228KB).
// ---------------------------------------------------------------------------
#define TSTR 136
#define GEMM_SMEM (2 * 2 * 16 * TSTR * 4)

__global__ __launch_bounds__(256, 2) void gemm_tf32(
    const float* __restrict__ A, const float* __restrict__ W,
    const float* __restrict__ bias, float* __restrict__ C,
    int M, int N, int Kiter, int Ksrc)
{
    extern __shared__ unsigned gsm[];
    // layout: As[2][16][TSTR], Bs[2][16][TSTR]
    unsigned* Asb = gsm;
    unsigned* Bsb = gsm + 2 * 16 * TSTR;

    const int tid = threadIdx.x;
    const int lane = tid & 31;
    const int wid = tid >> 5;
    const int wm = wid & 1;
    const int wn = wid >> 1;
    const int g  = lane >> 2;
    const int tg = lane & 3;
    const int mb = blockIdx.x * 128;
    const int nb = blockIdx.y * 128;

    const int fr = tid >> 1;
    const int fk = (tid & 1) * 8;

    const bool kvec = ((Ksrc & 3) == 0);

    const float* apb = A + (size_t)(mb + fr) * Ksrc + fk;
    const float* wpb = W + (size_t)(nb + fr) * Ksrc + fk;

    float c[4][4][4];
#pragma unroll
    for (int i = 0; i < 4; ++i)
#pragma unroll
        for (int j = 0; j < 4; ++j)
#pragma unroll
            for (int q = 0; q < 4; ++q) c[i][j][q] = 0.f;

    float av[8], wv[8];
    // load tile 0 into regs
    if (kvec) {
        float4 a0 = *(const float4*)(apb);
        float4 a1 = *(const float4*)(apb + 4);
        float4 w0 = *(const float4*)(wpb);
        float4 w1 = *(const float4*)(wpb + 4);
        av[0]=a0.x; av[1]=a0.y; av[2]=a0.z; av[3]=a0.w;
        av[4]=a1.x; av[5]=a1.y; av[6]=a1.z; av[7]=a1.w;
        wv[0]=w0.x; wv[1]=w0.y; wv[2]=w0.z; wv[3]=w0.w;
        wv[4]=w1.x; wv[5]=w1.y; wv[6]=w1.z; wv[7]=w1.w;
    } else {
#pragma unroll
        for (int j = 0; j < 8; ++j) {
            bool ok = (fk + j) < Ksrc;
            av[j] = ok ? apb[j] : 0.f;
            wv[j] = ok ? wpb[j] : 0.f;
        }
    }
    // store tile 0 into buffer 0
#pragma unroll
    for (int j = 0; j < 8; ++j) {
        Asb[(fk + j) * TSTR + fr] = tf32_(av[j]);
        Bsb[(fk + j) * TSTR + fr] = tf32_(wv[j]);
    }
    __syncthreads();

    int cur = 0;
    for (int k0 = 0; k0 < Kiter; k0 += 16) {
        const bool more = (k0 + 16) < Kiter;
        // prefetch next tile into regs (overlaps MMA below)
        if (more) {
            if (kvec) {
                float4 a0 = *(const float4*)(apb + k0 + 16);
                float4 a1 = *(const float4*)(apb + k0 + 20);
                float4 w0 = *(const float4*)(wpb + k0 + 16);
                float4 w1 = *(const float4*)(wpb + k0 + 20);
                av[0]=a0.x; av[1]=a0.y; av[2]=a0.z; av[3]=a0.w;
                av[4]=a1.x; av[5]=a1.y; av[6]=a1.z; av[7]=a1.w;
                wv[0]=w0.x; wv[1]=w0.y; wv[2]=w0.z; wv[3]=w0.w;
                wv[4]=w1.x; wv[5]=w1.y; wv[6]=w1.z; wv[7]=w1.w;
            } else {
#pragma unroll
                for (int j = 0; j < 8; ++j) {
                    bool ok = (k0 + 16 + fk + j) < Ksrc;
                    av[j] = ok ? apb[k0 + 16 + j] : 0.f;
                    wv[j] = ok ? wpb[k0 + 16 + j] : 0.f;
                }
            }
        }

        const unsigned* As = Asb + cur * (16 * TSTR);
        const unsigned* Bs = Bsb + cur * (16 * TSTR);
#pragma unroll
        for (int ks = 0; ks < 2; ++ks) {
            const int kk = ks * 8;
            unsigned bf[4][2];
#pragma unroll
            for (int j = 0; j < 4; ++j) {
                int cb = wn * 32 + j * 8 + g;
                bf[j][0] = Bs[(kk + tg) * TSTR + cb];
                bf[j][1] = Bs[(kk + tg + 4) * TSTR + cb];
            }
#pragma unroll
            for (int i = 0; i < 4; ++i) {
                int rb = wm * 64 + i * 16;
                unsigned af[4];
                af[0] = As[(kk + tg) * TSTR + rb + g];
                af[1] = As[(kk + tg) * TSTR + rb + g + 8];
                af[2] = As[(kk + tg + 4) * TSTR + rb + g];
                af[3] = As[(kk + tg + 4) * TSTR + rb + g + 8];
#pragma unroll
                for (int j = 0; j < 4; ++j)
                    mma_tf32(c[i][j], af, bf[j][0], bf[j][1]);
            }
        }

        // store prefetched tile into the OTHER buffer (read last iter, sealed
        // by the previous sync) while MMAs drain
        if (more) {
            unsigned* An = Asb + (cur ^ 1) * (16 * TSTR);
            unsigned* Bn = Bsb + (cur ^ 1) * (16 * TSTR);
#pragma unroll
            for (int j = 0; j < 8; ++j) {
                An[(fk + j) * TSTR + fr] = tf32_(av[j]);
                Bn[(fk + j) * TSTR + fr] = tf32_(wv[j]);
            }
        }
        __syncthreads();
        cur ^= 1;
    }

#pragma unroll
    for (int j = 0; j < 4; ++j) {
        int col = nb + wn * 32 + j * 8 + 2 * tg;
        float2 bb = *(const float2*)(bias + col);
#pragma unroll
        for (int i = 0; i < 4; ++i) {
            int row = mb + wm * 64 + i * 16 + g;
            float2 v0; v0.x = c[i][j][0] + bb.x; v0.y = c[i][j][1] + bb.y;
            float2 v1; v1.x = c[i][j][2] + bb.x; v1.y = c[i][j][3] + bb.y;
            *(float2*)(C + (size_t)row * N + col)       = v0;
            *(float2*)(C + (size_t)(row + 8) * N + col) = v1;
        }
    }
}

// ---------------------------------------------------------------------------
// GRU recurrence: R14 verbatim (best measured — do not touch).
// ---------------------------------------------------------------------------
#define RSTR 264
#define REC_W_FLOATS (192 * RSTR)
#define REC_SMEM ((192 * RSTR + 2 * 8 * RSTR) * 4)   // 219648 B

DEV_INLINE unsigned ctarank() { unsigned r; asm("mov.u32 %0, %%cluster_ctarank;" : "=r"(r)); return r; }
DEV_INLINE unsigned s2u(const void* p) {
    unsigned a;
    asm("{ .reg .u64 t; cvta.to.shared.u64 t, %1; cvt.u32.u64 %0, t; }" : "=r"(a) : "l"(p));
    return a;
}
DEV_INLINE unsigned mapa_(unsigned a, unsigned r) {
    unsigned o; asm("mapa.shared::cluster.u32 %0, %1, %2;" : "=r"(o) : "r"(a), "r"(r)); return o;
}
DEV_INLINE void st_cluster_u32(unsigned addr, unsigned v) {
    asm volatile("st.shared::cluster.u32 [%0], %1;" :: "r"(addr), "r"(v) : "memory");
}
DEV_INLINE void cl_arrive() { asm volatile("barrier.cluster.arrive.aligned;" ::: "memory"); }
DEV_INLINE void cl_wait()   { asm volatile("barrier.cluster.wait.aligned;"   ::: "memory"); }

__global__ __launch_bounds__(512, 1) void gru_rec(
    const float* __restrict__ xg, const float* __restrict__ W_hh,
    const float* __restrict__ b_hh, float* __restrict__ out_seq,
    float* __restrict__ hT, int layer0)
{
    extern __shared__ float smem[];
    float* w = smem;                        // [192 rows][264]
    float* hbase = smem + REC_W_FLOATS;     // [2 bufs][8 batches][264]

    const int tid = threadIdx.x;
    const unsigned rank = ctarank();
    const int cid = blockIdx.x >> 2;
    const int h_local = tid >> 3;
    const int bp = (tid >> 1) & 3;
    const int ks = tid & 1;
    const int h_glob = (int)rank * 64 + h_local;
    const int bsel = bp + 4 * ks;
    const int bglob = cid * 8 + bsel;
    const int hpoff = h_glob + ((h_glob >= 128) ? 4 : 0);

    for (int i = tid; i < 192 * 64; i += 512) {
        int row = i >> 6, kk = (i & 63) * 4;
        int grow = (row >> 6) * 256 + (int)rank * 64 + (row & 63);
        float4 v = ((const float4*)W_hh)[(size_t)grow * 64 + (kk >> 2)];
        *(float4*)(w + row * RSTR + kk + ((kk >= 128) ? 4 : 0)) = v;
    }
    for (int i = tid; i < 8 * RSTR; i += 512) hbase[i] = 0.f;

    const float bh_r = b_hh[h_glob];
    const float bh_z = b_hh[256 + h_glob];
    const float bh_n = b_hh[512 + h_glob];

    __syncthreads();
    cl_arrive(); cl_wait();

    unsigned hbase_u = s2u(hbase);
    unsigned pb[4];
#pragma unroll
    for (int q = 0; q < 4; ++q) pb[q] = mapa_(hbase_u, (unsigned)q);

    const int ko = ks * 132;
    const float* wr = w + h_local * RSTR + ko;
    const float* wz = wr + 64 * RSTR;
    const float* wn = wr + 128 * RSTR;

    const float* xrow = xg + (size_t)bglob * TT * G3;
    float xr = xrow[h_glob], xz = xrow[256 + h_glob], xn = xrow[512 + h_glob];

    float hp = 0.f;

    int p = 0;
    for (int t = 0; t < TT; ++t) {
        const float* h0r = hbase + (p * 8 + bp) * RSTR + ko;
        const float* h1r = h0r + 4 * RSTR;

        ull ar0 = 0, az0 = 0, an0 = 0, ar1 = 0, az1 = 0, an1 = 0;
#pragma unroll
        for (int k4 = 0; k4 < 32; ++k4) {
            ulonglong2 wrv = *(const ulonglong2*)(wr + 4 * k4);
            ulonglong2 wzv = *(const ulonglong2*)(wz + 4 * k4);
            ulonglong2 wnv = *(const ulonglong2*)(wn + 4 * k4);
            ulonglong2 h0v = *(const ulonglong2*)(h0r + 4 * k4);
            ulonglong2 h1v = *(const ulonglong2*)(h1r + 4 * k4);
            ar0 = fma2(wrv.x, h0v.x, ar0); ar0 = fma2(wrv.y, h0v.y, ar0);
            az0 = fma2(wzv.x, h0v.x, az0); az0 = fma2(wzv.y, h0v.y, az0);
            an0 = fma2(wnv.x, h0v.x, an0); an0 = fma2(wnv.y, h0v.y, an0);
            ar1 = fma2(wrv.x, h1v.x, ar1); ar1 = fma2(wrv.y, h1v.y, ar1);
            az1 = fma2(wzv.x, h1v.x, az1); az1 = fma2(wzv.y, h1v.y, az1);
            an1 = fma2(wnv.x, h1v.x, an1); an1 = fma2(wnv.y, h1v.y, an1);
        }
        float2 s;
        s = unpk(ar0); float fr0 = s.x + s.y;
        s = unpk(az0); float fz0 = s.x + s.y;
        s = unpk(an0); float fn0 = s.x + s.y;
        s = unpk(ar1); float fr1 = s.x + s.y;
        s = unpk(az1); float fz1 = s.x + s.y;
        s = unpk(an1); float fn1 = s.x + s.y;

        float sr = ks ? fr0 : fr1;
        float sz = ks ? fz0 : fz1;
        float sn = ks ? fn0 : fn1;
        float rr = __shfl_xor_sync(0xffffffffu, sr, 1);
        float rz = __shfl_xor_sync(0xffffffffu, sz, 1);
        float rn = __shfl_xor_sync(0xffffffffu, sn, 1);
        float hr = (ks ? fr1 : fr0) + rr;
        float hz = (ks ? fz1 : fz0) + rz;
        float hn = (ks ? fn1 : fn0) + rn;

        float r = sigm_(xr + bh_r + hr);
        float z = sigm_(xz + bh_z + hz);
        float n = tanh_(xn + r * (hn + bh_n));
        float hnew = (1.f - z) * n + z * hp;
        hp = hnew;

        unsigned off = (unsigned)(((1 - p) * 8 + bsel) * RSTR + hpoff) * 4u;
        unsigned hb = __float_as_uint(hnew);
        st_cluster_u32(pb[0] + off, hb);
        st_cluster_u32(pb[1] + off, hb);
        st_cluster_u32(pb[2] + off, hb);
        st_cluster_u32(pb[3] + off, hb);

        cl_arrive();

        if (t + 1 < TT) {
            const float* xp = xrow + (size_t)(t + 1) * G3;
            xr = xp[h_glob]; xz = xp[256 + h_glob]; xn = xp[512 + h_glob];
        }
        if (layer0) {
            out_seq[((size_t)bglob * TT + t) * HH + h_glob] = hnew;
        } else if (t == TT - 1) {
            hT[bglob * HH + h_glob] = hnew;
        }

        cl_wait();
        p ^= 1;
    }
}

// ---------------------------------------------------------------------------
// Launch helpers
// ---------------------------------------------------------------------------
static void launch_rec(const float* xg, const float* Whh, const float* bhh,
                       float* oseq, float* hT, int layer0)
{
    cudaFuncSetAttribute(gru_rec, cudaFuncAttributeMaxDynamicSharedMemorySize, REC_SMEM);
    cudaLaunchConfig_t cfg = {};
    cfg.gridDim = dim3(128, 1, 1);
    cfg.blockDim = dim3(512, 1, 1);
    cfg.dynamicSmemBytes = REC_SMEM;
    cfg.stream = 0;
    cudaLaunchAttribute at[1];
    at[0].id = cudaLaunchAttributeClusterDimension;
    at[0].val.clusterDim.x = 4;
    at[0].val.clusterDim.y = 1;
    at[0].val.clusterDim.z = 1;
    cfg.attrs = at;
    cfg.numAttrs = 1;
    cudaLaunchKernelEx(&cfg, gru_rec, xg, Whh, bhh, oseq, hT, layer0);
}

static void launch_gemm(const float* A, const float* W, const float* bias,
                        float* C, int M, int N, int Kiter, int Ksrc)
{
    cudaFuncSetAttribute(gemm_tf32, cudaFuncAttributeMaxDynamicSharedMemorySize, GEMM_SMEM);
    gemm_tf32<<<dim3(M / 128, N / 128), 256, GEMM_SMEM>>>(A, W, bias, C, M, N, Kiter, Ksrc);
}

extern "C" void kernel_launch(void* const* d_in, const int* in_sizes, int n_in,
                              void* d_out, int out_size)
{
    const float* x     = (const float*)d_in[0];
    const float* W_ih0 = (const float*)d_in[1];
    const float* W_hh0 = (const float*)d_in[2];
    const float* b_ih0 = (const float*)d_in[3];
    const float* b_hh0 = (const float*)d_in[4];
    const float* W_ih1 = (const float*)d_in[5];
    const float* W_hh1 = (const float*)d_in[6];
    const float* b_ih1 = (const float*)d_in[7];
    const float* b_hh1 = (const float*)d_in[8];
    const float* fc_W  = (const float*)d_in[9];
    const float* fc_b  = (const float*)d_in[10];
    float* out = (float*)d_out;

    float *xg, *o0, *hT;
    cudaGetSymbolAddress((void**)&xg, g_xg);
    cudaGetSymbolAddress((void**)&o0, g_out0);
    cudaGetSymbolAddress((void**)&hT, g_hT);

    const int M = BB * TT;  // 131072

    launch_gemm(x, W_ih0, b_ih0, xg, M, G3, 80, 75);
    launch_rec(xg, W_hh0, b_hh0, o0, nullptr, 1);
    launch_gemm(o0, W_ih1, b_ih1, xg, M, G3, 256, 256);
    launch_rec(xg, W_hh1, b_hh1, nullptr, hT, 0);
    launch_gemm(hT, fc_W, fc_b, out, BB, HH, HH, HH);
}